// round 2
// baseline (speedup 1.0000x reference)
#include <cuda_runtime.h>
#include <cuda_bf16.h>

#define B 32768
#define C 1000
#define NV4 250   // float4 per row (1000 floats)

__device__ int   g_cnt[C];
__device__ float g_row[B];

__global__ void zero_cnt_kernel() {
    int i = blockIdx.x * blockDim.x + threadIdx.x;
    if (i < C) g_cnt[i] = 0;
}

__global__ void hist_kernel(const int* __restrict__ label) {
    int i = blockIdx.x * blockDim.x + threadIdx.x;
    if (i < B) {
        int lab = label[i];
        lab = min(max(lab, 0), C - 1);
        atomicAdd(&g_cnt[lab], 1);
    }
}

__global__ __launch_bounds__(256) void row_kl_kernel(
    const float* __restrict__ f1,
    const float* __restrict__ f2,
    const int* __restrict__ label)
{
    __shared__ float sm1[8], sm2[8];
    __shared__ float ss1[8], ss2[8], sw[8];

    const int row = blockIdx.x;
    const int t   = threadIdx.x;
    const int w   = t >> 5;
    const int l   = t & 31;

    float4 a, b;
    if (t < NV4) {
        a = ((const float4*)f1)[(size_t)row * NV4 + t];
        b = ((const float4*)f2)[(size_t)row * NV4 + t];
    } else {
        a = make_float4(-1e30f, -1e30f, -1e30f, -1e30f);
        b = a;
    }

    // ---- pass 1: row maxes of f1 and f2 ----
    float m1 = fmaxf(fmaxf(a.x, a.y), fmaxf(a.z, a.w));
    float m2 = fmaxf(fmaxf(b.x, b.y), fmaxf(b.z, b.w));
    #pragma unroll
    for (int o = 16; o; o >>= 1) {
        m1 = fmaxf(m1, __shfl_xor_sync(0xFFFFFFFFu, m1, o));
        m2 = fmaxf(m2, __shfl_xor_sync(0xFFFFFFFFu, m2, o));
    }
    if (l == 0) { sm1[w] = m1; sm2[w] = m2; }
    __syncthreads();
    m1 = sm1[0]; m2 = sm2[0];
    #pragma unroll
    for (int i = 1; i < 8; i++) {
        m1 = fmaxf(m1, sm1[i]);
        m2 = fmaxf(m2, sm2[i]);
    }

    // ---- pass 2 (from registers): s1 = sum exp(f1-m1), s2 = sum exp(f2-m2),
    //      wv = sum exp(f2-m2) * (f2 - f1) ----
    float s1 = __expf(a.x - m1) + __expf(a.y - m1) + __expf(a.z - m1) + __expf(a.w - m1);
    float s2 = 0.f, wv = 0.f, e;
    e = __expf(b.x - m2); s2 += e; wv = fmaf(e, b.x - a.x, wv);
    e = __expf(b.y - m2); s2 += e; wv = fmaf(e, b.y - a.y, wv);
    e = __expf(b.z - m2); s2 += e; wv = fmaf(e, b.z - a.z, wv);
    e = __expf(b.w - m2); s2 += e; wv = fmaf(e, b.w - a.w, wv);

    #pragma unroll
    for (int o = 16; o; o >>= 1) {
        s1 += __shfl_xor_sync(0xFFFFFFFFu, s1, o);
        s2 += __shfl_xor_sync(0xFFFFFFFFu, s2, o);
        wv += __shfl_xor_sync(0xFFFFFFFFu, wv, o);
    }
    if (l == 0) { ss1[w] = s1; ss2[w] = s2; sw[w] = wv; }
    __syncthreads();

    if (t == 0) {
        float S1 = 0.f, S2 = 0.f, W = 0.f;
        #pragma unroll
        for (int i = 0; i < 8; i++) { S1 += ss1[i]; S2 += ss2[i]; W += sw[i]; }
        // KL = W/S2 + (m1 + log S1) - (m2 + log S2)
        float kl = W / S2 + (m1 + __logf(S1)) - (m2 + __logf(S2));
        int lab = label[row];
        lab = min(max(lab, 0), C - 1);
        int cnt = g_cnt[lab];
        g_row[row] = kl / ((float)max(cnt, 1) * (float)C);
    }
}

__global__ __launch_bounds__(1024) void reduce_kernel(float* __restrict__ out) {
    __shared__ float sred[32];
    const int t = threadIdx.x;
    float s = 0.f;
    #pragma unroll 8
    for (int i = t; i < B; i += 1024) s += g_row[i];
    #pragma unroll
    for (int o = 16; o; o >>= 1) s += __shfl_xor_sync(0xFFFFFFFFu, s, o);
    if ((t & 31) == 0) sred[t >> 5] = s;
    __syncthreads();
    if (t < 32) {
        s = sred[t];
        #pragma unroll
        for (int o = 16; o; o >>= 1) s += __shfl_xor_sync(0xFFFFFFFFu, s, o);
        if (t == 0) out[0] = s;
    }
}

extern "C" void kernel_launch(void* const* d_in, const int* in_sizes, int n_in,
                              void* d_out, int out_size)
{
    const float* f1    = (const float*)d_in[0];
    const float* f2    = (const float*)d_in[1];
    const int*   label = (const int*)d_in[2];
    float*       out   = (float*)d_out;

    zero_cnt_kernel<<<1, 1024>>>();
    hist_kernel<<<B / 256, 256>>>(label);
    row_kl_kernel<<<B, 256>>>(f1, f2, label);
    reduce_kernel<<<1, 1024>>>(out);
}

// round 3
// speedup vs baseline: 1.4082x; 1.4082x over previous
#include <cuda_runtime.h>
#include <cuda_bf16.h>

#define B 32768
#define C 1000
#define NV4 250            // float4 per row
#define NPART 32           // stage-A reduce blocks

__device__ int   g_cnt[C];
__device__ float g_row[B];
__device__ float g_part[NPART];

__global__ void zero_cnt_kernel() {
    int i = blockIdx.x * blockDim.x + threadIdx.x;
    if (i < C) g_cnt[i] = 0;
}

__global__ void hist_kernel(const int* __restrict__ label) {
    int i = blockIdx.x * blockDim.x + threadIdx.x;
    if (i < B) {
        int lab = label[i];
        lab = min(max(lab, 0), C - 1);
        atomicAdd(&g_cnt[lab], 1);
    }
}

// One row per warp: 8 warps/block, 4096 blocks. Each lane owns float4 slots
// j = lane + 32*k (k=0..7, j<250). All reductions are shfl; no smem/barriers.
__global__ __launch_bounds__(256) void row_kl_kernel(
    const float* __restrict__ f1,
    const float* __restrict__ f2)
{
    const int lane = threadIdx.x & 31;
    const int row  = blockIdx.x * 8 + (threadIdx.x >> 5);

    const float4* p1 = (const float4*)f1 + (size_t)row * NV4;
    const float4* p2 = (const float4*)f2 + (size_t)row * NV4;

    float4 a[8], b[8];
    const float4 NEG = make_float4(-1e30f, -1e30f, -1e30f, -1e30f);
    #pragma unroll
    for (int k = 0; k < 8; k++) {
        int j = lane + 32 * k;
        if (j < NV4) { a[k] = p1[j]; b[k] = p2[j]; }
        else         { a[k] = NEG;   b[k] = NEG;   }
    }

    // ---- row maxes ----
    float m1 = -1e30f, m2 = -1e30f;
    #pragma unroll
    for (int k = 0; k < 8; k++) {
        m1 = fmaxf(m1, fmaxf(fmaxf(a[k].x, a[k].y), fmaxf(a[k].z, a[k].w)));
        m2 = fmaxf(m2, fmaxf(fmaxf(b[k].x, b[k].y), fmaxf(b[k].z, b[k].w)));
    }
    #pragma unroll
    for (int o = 16; o; o >>= 1) {
        m1 = fmaxf(m1, __shfl_xor_sync(0xFFFFFFFFu, m1, o));
        m2 = fmaxf(m2, __shfl_xor_sync(0xFFFFFFFFu, m2, o));
    }

    // ---- s1 = sum exp(f1-m1); s2 = sum exp(f2-m2); wv = sum exp(f2-m2)*(f2-f1) ----
    float s1 = 0.f, s2 = 0.f, wv = 0.f;
    #pragma unroll
    for (int k = 0; k < 8; k++) {
        s1 += __expf(a[k].x - m1) + __expf(a[k].y - m1)
            + __expf(a[k].z - m1) + __expf(a[k].w - m1);
        float e;
        e = __expf(b[k].x - m2); s2 += e; wv = fmaf(e, b[k].x - a[k].x, wv);
        e = __expf(b[k].y - m2); s2 += e; wv = fmaf(e, b[k].y - a[k].y, wv);
        e = __expf(b[k].z - m2); s2 += e; wv = fmaf(e, b[k].z - a[k].z, wv);
        e = __expf(b[k].w - m2); s2 += e; wv = fmaf(e, b[k].w - a[k].w, wv);
    }
    #pragma unroll
    for (int o = 16; o; o >>= 1) {
        s1 += __shfl_xor_sync(0xFFFFFFFFu, s1, o);
        s2 += __shfl_xor_sync(0xFFFFFFFFu, s2, o);
        wv += __shfl_xor_sync(0xFFFFFFFFu, wv, o);
    }

    if (lane == 0) {
        // KL = wv/s2 + (m1 + log s1) - (m2 + log s2)
        g_row[row] = wv / s2 + (m1 + __logf(s1)) - (m2 + __logf(s2));
    }
}

// Stage A: 32 blocks x 256 threads; thread i handles rows 4i..4i+3 (one
// float4 of g_row + one int4 of labels), applies 1/(cnt*C), block-reduces.
__global__ __launch_bounds__(256) void reduceA_kernel(const int* __restrict__ label) {
    __shared__ float sred[8];
    const int t   = threadIdx.x;
    const int idx = blockIdx.x * 256 + t;          // float4 index into g_row

    float4 v = ((const float4*)g_row)[idx];
    int4   L = ((const int4*)label)[idx];

    const float invC = 1.0f / (float)C;
    float s = 0.f;
    s += v.x * invC / (float)max(g_cnt[min(max(L.x, 0), C - 1)], 1);
    s += v.y * invC / (float)max(g_cnt[min(max(L.y, 0), C - 1)], 1);
    s += v.z * invC / (float)max(g_cnt[min(max(L.z, 0), C - 1)], 1);
    s += v.w * invC / (float)max(g_cnt[min(max(L.w, 0), C - 1)], 1);

    #pragma unroll
    for (int o = 16; o; o >>= 1) s += __shfl_xor_sync(0xFFFFFFFFu, s, o);
    if ((t & 31) == 0) sred[t >> 5] = s;
    __syncthreads();
    if (t == 0) {
        float r = 0.f;
        #pragma unroll
        for (int i = 0; i < 8; i++) r += sred[i];
        g_part[blockIdx.x] = r;
    }
}

__global__ void reduceB_kernel(float* __restrict__ out) {
    const int t = threadIdx.x;
    float s = g_part[t];
    #pragma unroll
    for (int o = 16; o; o >>= 1) s += __shfl_xor_sync(0xFFFFFFFFu, s, o);
    if (t == 0) out[0] = s;
}

extern "C" void kernel_launch(void* const* d_in, const int* in_sizes, int n_in,
                              void* d_out, int out_size)
{
    const float* f1    = (const float*)d_in[0];
    const float* f2    = (const float*)d_in[1];
    const int*   label = (const int*)d_in[2];
    float*       out   = (float*)d_out;

    zero_cnt_kernel<<<1, 1024>>>();
    hist_kernel<<<B / 256, 256>>>(label);
    row_kl_kernel<<<B / 8, 256>>>(f1, f2);
    reduceA_kernel<<<NPART, 256>>>(label);
    reduceB_kernel<<<1, 32>>>(out);
}

// round 4
// speedup vs baseline: 1.4471x; 1.0276x over previous
#include <cuda_runtime.h>
#include <cuda_bf16.h>

#define B 32768
#define C 1000
#define NV4 250            // float4 per row
#define NBLK (B / 8)       // 4096 row_kl blocks (8 rows/block, 1 row/warp)

__device__ int   g_cnt[C];
__device__ float g_part[NBLK];

// Single-block privatized histogram: zero smem, count, plain-store to g_cnt.
// Replaces zero_cnt + hist (no global zeroing pass needed).
__global__ __launch_bounds__(1024) void hist_kernel(const int* __restrict__ label) {
    __shared__ int h[C];
    const int t = threadIdx.x;
    for (int i = t; i < C; i += 1024) h[i] = 0;
    __syncthreads();
    // 32768 labels = 8192 int4; 1024 threads x 8 int4 each, coalesced.
    #pragma unroll
    for (int k = 0; k < 8; k++) {
        int4 L = ((const int4*)label)[t + 1024 * k];
        atomicAdd(&h[min(max(L.x, 0), C - 1)], 1);
        atomicAdd(&h[min(max(L.y, 0), C - 1)], 1);
        atomicAdd(&h[min(max(L.z, 0), C - 1)], 1);
        atomicAdd(&h[min(max(L.w, 0), C - 1)], 1);
    }
    __syncthreads();
    for (int i = t; i < C; i += 1024) g_cnt[i] = h[i];
}

// One row per warp, 8 warps/block. Lane j owns float4 slots j+32k (k=0..7).
// Scale by 1/(cnt[label]*C) in-kernel; block-reduce 8 warp values -> g_part.
__global__ __launch_bounds__(256) void row_kl_kernel(
    const float* __restrict__ f1,
    const float* __restrict__ f2,
    const int* __restrict__ label)
{
    __shared__ float swarp[8];
    const int lane = threadIdx.x & 31;
    const int wid  = threadIdx.x >> 5;
    const int row  = blockIdx.x * 8 + wid;

    const float4* p1 = (const float4*)f1 + (size_t)row * NV4;
    const float4* p2 = (const float4*)f2 + (size_t)row * NV4;

    float4 a[8], b[8];
    const float4 NEG = make_float4(-1e30f, -1e30f, -1e30f, -1e30f);
    #pragma unroll
    for (int k = 0; k < 8; k++) {
        int j = lane + 32 * k;
        if (j < NV4) { a[k] = p1[j]; b[k] = p2[j]; }
        else         { a[k] = NEG;   b[k] = NEG;   }
    }

    // ---- row maxes ----
    float m1 = -1e30f, m2 = -1e30f;
    #pragma unroll
    for (int k = 0; k < 8; k++) {
        m1 = fmaxf(m1, fmaxf(fmaxf(a[k].x, a[k].y), fmaxf(a[k].z, a[k].w)));
        m2 = fmaxf(m2, fmaxf(fmaxf(b[k].x, b[k].y), fmaxf(b[k].z, b[k].w)));
    }
    #pragma unroll
    for (int o = 16; o; o >>= 1) {
        m1 = fmaxf(m1, __shfl_xor_sync(0xFFFFFFFFu, m1, o));
        m2 = fmaxf(m2, __shfl_xor_sync(0xFFFFFFFFu, m2, o));
    }

    // ---- s1 = sum exp(f1-m1); s2 = sum exp(f2-m2); wv = sum e2*(f2-f1) ----
    float s1 = 0.f, s2 = 0.f, wv = 0.f;
    #pragma unroll
    for (int k = 0; k < 8; k++) {
        s1 += __expf(a[k].x - m1) + __expf(a[k].y - m1)
            + __expf(a[k].z - m1) + __expf(a[k].w - m1);
        float e;
        e = __expf(b[k].x - m2); s2 += e; wv = fmaf(e, b[k].x - a[k].x, wv);
        e = __expf(b[k].y - m2); s2 += e; wv = fmaf(e, b[k].y - a[k].y, wv);
        e = __expf(b[k].z - m2); s2 += e; wv = fmaf(e, b[k].z - a[k].z, wv);
        e = __expf(b[k].w - m2); s2 += e; wv = fmaf(e, b[k].w - a[k].w, wv);
    }
    #pragma unroll
    for (int o = 16; o; o >>= 1) {
        s1 += __shfl_xor_sync(0xFFFFFFFFu, s1, o);
        s2 += __shfl_xor_sync(0xFFFFFFFFu, s2, o);
        wv += __shfl_xor_sync(0xFFFFFFFFu, wv, o);
    }

    if (lane == 0) {
        float kl = wv / s2 + (m1 + __logf(s1)) - (m2 + __logf(s2));
        int lab = min(max(label[row], 0), C - 1);
        float cnt = (float)max(g_cnt[lab], 1);
        swarp[wid] = kl / (cnt * (float)C);
    }
    __syncthreads();
    if (threadIdx.x == 0) {
        float r = 0.f;
        #pragma unroll
        for (int i = 0; i < 8; i++) r += swarp[i];
        g_part[blockIdx.x] = r;
    }
}

// Final: 4096 partials -> scalar. One block, 1024 threads, float4 loads.
__global__ __launch_bounds__(1024) void reduce_kernel(float* __restrict__ out) {
    __shared__ float sred[32];
    const int t = threadIdx.x;
    float4 v = ((const float4*)g_part)[t];
    float s = (v.x + v.y) + (v.z + v.w);
    #pragma unroll
    for (int o = 16; o; o >>= 1) s += __shfl_xor_sync(0xFFFFFFFFu, s, o);
    if ((t & 31) == 0) sred[t >> 5] = s;
    __syncthreads();
    if (t < 32) {
        s = sred[t];
        #pragma unroll
        for (int o = 16; o; o >>= 1) s += __shfl_xor_sync(0xFFFFFFFFu, s, o);
        if (t == 0) out[0] = s;
    }
}

extern "C" void kernel_launch(void* const* d_in, const int* in_sizes, int n_in,
                              void* d_out, int out_size)
{
    const float* f1    = (const float*)d_in[0];
    const float* f2    = (const float*)d_in[1];
    const int*   label = (const int*)d_in[2];
    float*       out   = (float*)d_out;

    hist_kernel<<<1, 1024>>>(label);
    row_kl_kernel<<<NBLK, 256>>>(f1, f2, label);
    reduce_kernel<<<1, 1024>>>(out);
}

// round 5
// speedup vs baseline: 1.4545x; 1.0052x over previous
#include <cuda_runtime.h>
#include <cuda_bf16.h>

#define B 32768
#define C 1000
#define NV4 250            // float4 per row
#define NBLK (B / 8)       // 4096 row_kl blocks (8 rows/block, 1 row/warp)

// INVARIANT: g_cnt == 0 at every kernel_launch entry.
// Zero-initialized at module load; re-zeroed by reduce_kernel's tail each call.
__device__ int   g_cnt[C];
__device__ float g_part[NBLK];

// Parallel histogram: 64 blocks x 128 threads, one int4 of labels per thread,
// direct global atomics (32768 increments spread over 1000 addresses).
__global__ __launch_bounds__(128) void hist_kernel(const int* __restrict__ label) {
    int i = blockIdx.x * 128 + threadIdx.x;          // int4 index, 8192 total
    int4 L = ((const int4*)label)[i];
    atomicAdd(&g_cnt[min(max(L.x, 0), C - 1)], 1);
    atomicAdd(&g_cnt[min(max(L.y, 0), C - 1)], 1);
    atomicAdd(&g_cnt[min(max(L.z, 0), C - 1)], 1);
    atomicAdd(&g_cnt[min(max(L.w, 0), C - 1)], 1);
}

// One row per warp, 8 warps/block. Lane j owns float4 slots j+32k (k=0..7).
// Scale by 1/(cnt[label]*C) in-kernel; block-reduce 8 warp values -> g_part.
__global__ __launch_bounds__(256) void row_kl_kernel(
    const float* __restrict__ f1,
    const float* __restrict__ f2,
    const int* __restrict__ label)
{
    __shared__ float swarp[8];
    const int lane = threadIdx.x & 31;
    const int wid  = threadIdx.x >> 5;
    const int row  = blockIdx.x * 8 + wid;

    const float4* p1 = (const float4*)f1 + (size_t)row * NV4;
    const float4* p2 = (const float4*)f2 + (size_t)row * NV4;

    float4 a[8], b[8];
    const float4 NEG = make_float4(-1e30f, -1e30f, -1e30f, -1e30f);
    #pragma unroll
    for (int k = 0; k < 8; k++) {
        int j = lane + 32 * k;
        if (j < NV4) { a[k] = p1[j]; b[k] = p2[j]; }
        else         { a[k] = NEG;   b[k] = NEG;   }
    }

    // ---- row maxes ----
    float m1 = -1e30f, m2 = -1e30f;
    #pragma unroll
    for (int k = 0; k < 8; k++) {
        m1 = fmaxf(m1, fmaxf(fmaxf(a[k].x, a[k].y), fmaxf(a[k].z, a[k].w)));
        m2 = fmaxf(m2, fmaxf(fmaxf(b[k].x, b[k].y), fmaxf(b[k].z, b[k].w)));
    }
    #pragma unroll
    for (int o = 16; o; o >>= 1) {
        m1 = fmaxf(m1, __shfl_xor_sync(0xFFFFFFFFu, m1, o));
        m2 = fmaxf(m2, __shfl_xor_sync(0xFFFFFFFFu, m2, o));
    }

    // ---- s1 = sum exp(f1-m1); s2 = sum exp(f2-m2); wv = sum e2*(f2-f1) ----
    float s1 = 0.f, s2 = 0.f, wv = 0.f;
    #pragma unroll
    for (int k = 0; k < 8; k++) {
        s1 += __expf(a[k].x - m1) + __expf(a[k].y - m1)
            + __expf(a[k].z - m1) + __expf(a[k].w - m1);
        float e;
        e = __expf(b[k].x - m2); s2 += e; wv = fmaf(e, b[k].x - a[k].x, wv);
        e = __expf(b[k].y - m2); s2 += e; wv = fmaf(e, b[k].y - a[k].y, wv);
        e = __expf(b[k].z - m2); s2 += e; wv = fmaf(e, b[k].z - a[k].z, wv);
        e = __expf(b[k].w - m2); s2 += e; wv = fmaf(e, b[k].w - a[k].w, wv);
    }
    #pragma unroll
    for (int o = 16; o; o >>= 1) {
        s1 += __shfl_xor_sync(0xFFFFFFFFu, s1, o);
        s2 += __shfl_xor_sync(0xFFFFFFFFu, s2, o);
        wv += __shfl_xor_sync(0xFFFFFFFFu, wv, o);
    }

    if (lane == 0) {
        float kl = wv / s2 + (m1 + __logf(s1)) - (m2 + __logf(s2));
        int lab = min(max(label[row], 0), C - 1);
        float cnt = (float)max(g_cnt[lab], 1);
        swarp[wid] = kl / (cnt * (float)C);
    }
    __syncthreads();
    if (threadIdx.x == 0) {
        float r = 0.f;
        #pragma unroll
        for (int i = 0; i < 8; i++) r += swarp[i];
        g_part[blockIdx.x] = r;
    }
}

// Final: 4096 partials -> scalar, and re-zero g_cnt for the next call/replay
// (g_cnt is no longer read after row_kl_kernel, so this is safe).
__global__ __launch_bounds__(1024) void reduce_kernel(float* __restrict__ out) {
    __shared__ float sred[32];
    const int t = threadIdx.x;
    if (t < C) g_cnt[t] = 0;          // maintain entry invariant

    float4 v = ((const float4*)g_part)[t];
    float s = (v.x + v.y) + (v.z + v.w);
    #pragma unroll
    for (int o = 16; o; o >>= 1) s += __shfl_xor_sync(0xFFFFFFFFu, s, o);
    if ((t & 31) == 0) sred[t >> 5] = s;
    __syncthreads();
    if (t < 32) {
        s = sred[t];
        #pragma unroll
        for (int o = 16; o; o >>= 1) s += __shfl_xor_sync(0xFFFFFFFFu, s, o);
        if (t == 0) out[0] = s;
    }
}

extern "C" void kernel_launch(void* const* d_in, const int* in_sizes, int n_in,
                              void* d_out, int out_size)
{
    const float* f1    = (const float*)d_in[0];
    const float* f2    = (const float*)d_in[1];
    const int*   label = (const int*)d_in[2];
    float*       out   = (float*)d_out;

    hist_kernel<<<64, 128>>>(label);
    row_kl_kernel<<<NBLK, 256>>>(f1, f2, label);
    reduce_kernel<<<1, 1024>>>(out);
}